// round 1
// baseline (speedup 1.0000x reference)
#include <cuda_runtime.h>
#include <math.h>

#define NN   10000
#define EE   160000
#define GG   128
#define HID  25
#define DOUT 32
#define NT   4
#define BEPS 1e-5f

// ---------------- scratch (static device allocations; no cudaMalloc) -------
__device__ float  d_h[(size_t)HID * EE];        // h pre-BN, layout [k][e]
__device__ double d_sum[HID];
__device__ double d_sumsq[HID];
__device__ float  d_scale[HID];
__device__ float  d_shift[HID];
__device__ float  d_y[(size_t)NN * HID * DOUT]; // y[n][k][o]
__device__ float  d_xb[NN * DOUT];              // x[n] @ reshape(b2)
__device__ float  d_agg[NN * DOUT];
__device__ float  d_x0[NN * DOUT];
__device__ float  d_x1[NN * DOUT];
__device__ float  d_deg[NN];
__device__ float  d_gsum[GG * DOUT];
__device__ float  d_gcnt[GG];

// ---------------- degree ----------------------------------------------------
__global__ void k_zero_deg() {
    int i = blockIdx.x * blockDim.x + threadIdx.x;
    if (i < NN) d_deg[i] = 0.f;
}

__global__ void k_deg(const int* __restrict__ ei) {
    int e = blockIdx.x * blockDim.x + threadIdx.x;
    if (e < EE) atomicAdd(&d_deg[ei[EE + e]], 1.f);
}

__global__ void k_zero_stats() {
    int t = threadIdx.x;
    if (t < HID) { d_sum[t] = 0.0; d_sumsq[t] = 0.0; }
}

// ---------------- edge MLP first linear + BN statistics ---------------------
// grid = (E/256, HID); each block handles one fixed column k -> clean reduce.
__global__ void k_h(const float* __restrict__ ea, const float* __restrict__ w1,
                    const float* __restrict__ b1) {
    int k = blockIdx.y;
    int e = blockIdx.x * blockDim.x + threadIdx.x;
    float v = 0.f;
    if (e < EE) {
        float a0 = ea[3 * e + 0], a1 = ea[3 * e + 1], a2 = ea[3 * e + 2];
        v = fmaf(a0, __ldg(&w1[k]),
            fmaf(a1, __ldg(&w1[HID + k]),
            fmaf(a2, __ldg(&w1[2 * HID + k]), __ldg(&b1[k]))));
        d_h[(size_t)k * EE + e] = v;
    }
    // block reduction of (v, v*v)
    float s = v, q = v * v;
#pragma unroll
    for (int off = 16; off; off >>= 1) {
        s += __shfl_down_sync(0xffffffffu, s, off);
        q += __shfl_down_sync(0xffffffffu, q, off);
    }
    __shared__ float ss[8], sq[8];
    int lane = threadIdx.x & 31, wid = threadIdx.x >> 5;
    if (lane == 0) { ss[wid] = s; sq[wid] = q; }
    __syncthreads();
    if (threadIdx.x == 0) {
        float S = 0.f, Q = 0.f;
#pragma unroll
        for (int w = 0; w < 8; w++) { S += ss[w]; Q += sq[w]; }
        atomicAdd(&d_sum[k],   (double)S);
        atomicAdd(&d_sumsq[k], (double)Q);
    }
}

// Fold BN (+gamma/beta) into per-column affine: hn = relu(h*scale + shift)
__global__ void k_bn(const float* __restrict__ g, const float* __restrict__ be) {
    int k = threadIdx.x;
    if (k < HID) {
        double mu  = d_sum[k]   / (double)EE;
        double var = d_sumsq[k] / (double)EE - mu * mu;
        float rs = rsqrtf((float)var + BEPS);
        float sc = rs * g[k];
        d_scale[k] = sc;
        d_shift[k] = be[k] - (float)mu * sc;
    }
}

// ---------------- per-node precompute: y[n,k,o] = sum_i x[n,i] w2[k,i,o] ----
// w2 fully in smem; NT nodes per tile so each smem read feeds NT FMAs.
// Also computes xb[n,o] = sum_i x[n,i] b2[i*DOUT+o] and zeroes agg.
template <int DIN>
__global__ void k_y(const float* __restrict__ xin_ext, int use_ext,
                    const float* __restrict__ w2, const float* __restrict__ b2) {
    extern __shared__ float sm[];
    float* w2s = sm;                           // HID*DIN*DOUT
    float* b2s = w2s + HID * DIN * DOUT;       // DIN*DOUT
    float* xs  = b2s + DIN * DOUT;             // NT*DIN
    const float* xin = use_ext ? xin_ext : d_x0;
    int tid = threadIdx.x;
    for (int i = tid; i < HID * DIN * DOUT; i += blockDim.x) w2s[i] = w2[i];
    for (int i = tid; i < DIN * DOUT; i += blockDim.x)       b2s[i] = b2[i];
    __syncthreads();

    for (int n0 = blockIdx.x * NT; n0 < NN; n0 += gridDim.x * NT) {
        for (int i = tid; i < NT * DIN; i += blockDim.x) {
            int n = n0 + i / DIN;
            xs[i] = (n < NN) ? xin[(size_t)n * DIN + (i % DIN)] : 0.f;
        }
        __syncthreads();

        for (int p = tid; p < HID * DOUT; p += blockDim.x) {
            int k = p / DOUT, o = p % DOUT;
            float a0 = 0.f, a1 = 0.f, a2 = 0.f, a3 = 0.f;
#pragma unroll
            for (int i = 0; i < DIN; i++) {
                float w = w2s[(k * DIN + i) * DOUT + o];
                a0 = fmaf(xs[0 * DIN + i], w, a0);
                a1 = fmaf(xs[1 * DIN + i], w, a1);
                a2 = fmaf(xs[2 * DIN + i], w, a2);
                a3 = fmaf(xs[3 * DIN + i], w, a3);
            }
            if (n0 + 0 < NN) d_y[((size_t)(n0 + 0) * HID + k) * DOUT + o] = a0;
            if (n0 + 1 < NN) d_y[((size_t)(n0 + 1) * HID + k) * DOUT + o] = a1;
            if (n0 + 2 < NN) d_y[((size_t)(n0 + 2) * HID + k) * DOUT + o] = a2;
            if (n0 + 3 < NN) d_y[((size_t)(n0 + 3) * HID + k) * DOUT + o] = a3;
        }
        for (int p = tid; p < NT * DOUT; p += blockDim.x) {
            int t = p / DOUT, o = p % DOUT;
            int n = n0 + t;
            if (n < NN) {
                float acc = 0.f;
#pragma unroll
                for (int i = 0; i < DIN; i++)
                    acc = fmaf(xs[t * DIN + i], b2s[i * DOUT + o], acc);
                d_xb[n * DOUT + o]  = acc;
                d_agg[n * DOUT + o] = 0.f;
            }
        }
        __syncthreads();
    }
}

// ---------------- edge messages: warp per edge, lane = out channel ----------
__global__ void k_msg(const int* __restrict__ ei) {
    __shared__ float ssc[HID], ssh[HID];
    if (threadIdx.x < HID) {
        ssc[threadIdx.x] = d_scale[threadIdx.x];
        ssh[threadIdx.x] = d_shift[threadIdx.x];
    }
    __syncthreads();
    int gw   = (blockIdx.x * blockDim.x + threadIdx.x) >> 5;
    int lane = threadIdx.x & 31;
    if (gw >= EE) return;
    int src = ei[gw], dst = ei[EE + gw];
    float m = d_xb[src * DOUT + lane];
    const float* yrow = d_y + (size_t)src * HID * DOUT;
#pragma unroll
    for (int k = 0; k < HID; k++) {
        float hv = __ldg(&d_h[(size_t)k * EE + gw]);        // broadcast within warp
        hv = fmaxf(fmaf(hv, ssc[k], ssh[k]), 0.f);          // BN + relu
        m  = fmaf(hv, yrow[k * DOUT + lane], m);            // coalesced 128B
    }
    atomicAdd(&d_agg[dst * DOUT + lane], m);
}

// ---------------- node update: scatter-mean + root transform + ELU ----------
template <int DIN>
__global__ void k_x(const float* __restrict__ xin_ext, int use_ext,
                    const float* __restrict__ wr, const float* __restrict__ bc,
                    int outsel) {
    int idx = blockIdx.x * blockDim.x + threadIdx.x;
    if (idx >= NN * DOUT) return;
    int n = idx / DOUT, o = idx % DOUT;
    const float* xin = use_ext ? xin_ext : d_x0;
    float root = __ldg(&bc[o]);
#pragma unroll
    for (int i = 0; i < DIN; i++)
        root = fmaf(xin[(size_t)n * DIN + i], __ldg(&wr[i * DOUT + o]), root);
    float dg = fmaxf(d_deg[n], 1.f);
    float v = d_agg[idx] / dg + root;
    v = (v > 0.f) ? v : expm1f(v);
    (outsel ? d_x1 : d_x0)[idx] = v;
}

// ---------------- global mean pool + fc -------------------------------------
__global__ void kp_zero() {
    int i = blockIdx.x * blockDim.x + threadIdx.x;
    if (i < GG * DOUT) d_gsum[i] = 0.f;
    if (i < GG)        d_gcnt[i] = 0.f;
}

__global__ void kp_acc(const int* __restrict__ batch) {
    int gw   = (blockIdx.x * blockDim.x + threadIdx.x) >> 5;
    int lane = threadIdx.x & 31;
    if (gw >= NN) return;
    int b = batch[gw];
    atomicAdd(&d_gsum[b * DOUT + lane], d_x1[gw * DOUT + lane]);
    if (lane == 0) atomicAdd(&d_gcnt[b], 1.f);
}

__global__ void kp_out(const float* __restrict__ wfc, const float* __restrict__ bfc,
                       float* __restrict__ out) {
    int g = threadIdx.x;
    if (g < GG) {
        float c = fmaxf(d_gcnt[g], 1.f);
        float acc = 0.f;
#pragma unroll
        for (int o = 0; o < DOUT; o++)
            acc = fmaf(d_gsum[g * DOUT + o] / c, __ldg(&wfc[o]), acc);
        out[g] = acc + bfc[0];
    }
}

// ---------------- launch -----------------------------------------------------
extern "C" void kernel_launch(void* const* d_in, const int* in_sizes, int n_in,
                              void* d_out, int out_size) {
    (void)in_sizes; (void)n_in; (void)out_size;
    const float* x     = (const float*)d_in[0];
    const float* ea    = (const float*)d_in[1];
    const int*   ei    = (const int*)d_in[2];
    const int*   batch = (const int*)d_in[3];
    const float* w1_0 = (const float*)d_in[4];
    const float* b1_0 = (const float*)d_in[5];
    const float* g_0  = (const float*)d_in[6];
    const float* be_0 = (const float*)d_in[7];
    const float* w2_0 = (const float*)d_in[8];
    const float* b2_0 = (const float*)d_in[9];
    const float* wr_0 = (const float*)d_in[10];
    const float* bc_0 = (const float*)d_in[11];
    const float* w1_1 = (const float*)d_in[12];
    const float* b1_1 = (const float*)d_in[13];
    const float* g_1  = (const float*)d_in[14];
    const float* be_1 = (const float*)d_in[15];
    const float* w2_1 = (const float*)d_in[16];
    const float* b2_1 = (const float*)d_in[17];
    const float* wr_1 = (const float*)d_in[18];
    const float* bc_1 = (const float*)d_in[19];
    const float* wfc  = (const float*)d_in[20];
    const float* bfc  = (const float*)d_in[21];
    float* out = (float*)d_out;

    cudaFuncSetAttribute(k_y<16>, cudaFuncAttributeMaxDynamicSharedMemorySize, 64 * 1024);
    cudaFuncSetAttribute(k_y<32>, cudaFuncAttributeMaxDynamicSharedMemorySize, 112 * 1024);
    int smem0 = (HID * 16 * DOUT + 16 * DOUT + NT * 16) * (int)sizeof(float); //  53.5 KB
    int smem1 = (HID * 32 * DOUT + 32 * DOUT + NT * 32) * (int)sizeof(float); // 107.0 KB

    k_zero_deg<<<(NN + 255) / 256, 256>>>();
    k_deg<<<(EE + 255) / 256, 256>>>(ei);

    // ---- layer 0 (din=16) ----
    k_zero_stats<<<1, 32>>>();
    k_h<<<dim3((EE + 255) / 256, HID), 256>>>(ea, w1_0, b1_0);
    k_bn<<<1, 32>>>(g_0, be_0);
    k_y<16><<<296, 256, smem0>>>(x, 1, w2_0, b2_0);
    k_msg<<<(EE * 32 + 255) / 256, 256>>>(ei);
    k_x<16><<<(NN * DOUT + 255) / 256, 256>>>(x, 1, wr_0, bc_0, 0);

    // ---- layer 1 (din=32) ----
    k_zero_stats<<<1, 32>>>();
    k_h<<<dim3((EE + 255) / 256, HID), 256>>>(ea, w1_1, b1_1);
    k_bn<<<1, 32>>>(g_1, be_1);
    k_y<32><<<296, 256, smem1>>>(nullptr, 0, w2_1, b2_1);
    k_msg<<<(EE * 32 + 255) / 256, 256>>>(ei);
    k_x<32><<<(NN * DOUT + 255) / 256, 256>>>(nullptr, 0, wr_1, bc_1, 1);

    // ---- pool + fc ----
    kp_zero<<<(GG * DOUT + 255) / 256, 256>>>();
    kp_acc<<<(NN * 32 + 255) / 256, 256>>>(batch);
    kp_out<<<1, 128>>>(wfc, bfc, out);
}

// round 2
// speedup vs baseline: 1.1499x; 1.1499x over previous
#include <cuda_runtime.h>
#include <math.h>

#define NN   10000
#define EE   160000
#define GG   128
#define HID  25
#define DOUT 32
#define NT   4
#define BEPS 1e-5f

// ---------------- scratch ----------------------------------------------------
__device__ float  d_h[(size_t)EE * HID];        // h pre-BN, sorted-by-src order, [p][k]
__device__ double d_sum[2 * HID];               // BN sum / sumsq
__device__ float  d_scale[HID];
__device__ float  d_shift[HID];
__device__ float  d_y[(size_t)NN * HID * DOUT]; // y[n][k][o]
__device__ float  d_xb[NN * DOUT];
__device__ float  d_agg[NN * DOUT];
__device__ float  d_x0[NN * DOUT];
__device__ float  d_x1[NN * DOUT];
__device__ float  d_deg[NN];                    // dst in-degree (float, for mean)
__device__ int    d_degs[NN];                   // src out-degree
__device__ int    d_start[NN + 1];              // CSR row starts (by src)
__device__ int    d_cursor[NN];
__device__ int    d_perm[EE];                   // sorted pos -> original edge id
__device__ int    d_dsts[EE];                   // dst per sorted pos
__device__ float  d_gsum[GG * DOUT];
__device__ float  d_gcnt[GG];

// ---------------- setup: zero everything that needs it -----------------------
__global__ void k_init() {
    int i = blockIdx.x * blockDim.x + threadIdx.x;
    if (i < NN)        { d_deg[i] = 0.f; d_degs[i] = 0; }
    if (i < 2 * HID)   d_sum[i] = 0.0;
    if (i < GG * DOUT) d_gsum[i] = 0.f;
    if (i < GG)        d_gcnt[i] = 0.f;
}

__global__ void k_deg(const int* __restrict__ ei) {
    int e = blockIdx.x * blockDim.x + threadIdx.x;
    if (e < EE) {
        atomicAdd(&d_deg[ei[EE + e]], 1.f);
        atomicAdd(&d_degs[ei[e]], 1);
    }
}

// single-block exclusive scan of d_degs -> d_start / d_cursor
__global__ void k_scan() {
    __shared__ int s[1024];
    const int t = threadIdx.x;
    const int CH = (NN + 1023) / 1024;   // 10
    int loc[CH];
    int base = t * CH;
    int run = 0;
#pragma unroll
    for (int i = 0; i < CH; i++) {
        int v = (base + i < NN) ? d_degs[base + i] : 0;
        loc[i] = run;
        run += v;
    }
    s[t] = run;
    __syncthreads();
    for (int off = 1; off < 1024; off <<= 1) {
        int v = (t >= off) ? s[t - off] : 0;
        __syncthreads();
        s[t] += v;
        __syncthreads();
    }
    int excl = (t > 0) ? s[t - 1] : 0;
#pragma unroll
    for (int i = 0; i < CH; i++) {
        if (base + i < NN) {
            int v = excl + loc[i];
            d_start[base + i]  = v;
            d_cursor[base + i] = v;
        }
    }
    if (t == 1023) d_start[NN] = s[1023];
}

__global__ void k_scatter(const int* __restrict__ ei) {
    int e = blockIdx.x * blockDim.x + threadIdx.x;
    if (e < EE) {
        int src = ei[e];
        int pos = atomicAdd(&d_cursor[src], 1);
        d_perm[pos] = e;
        d_dsts[pos] = ei[EE + e];
    }
}

// ---------------- edge MLP first linear (sorted order) + BN statistics -------
// one thread per sorted edge position; smem-staged coalesced h stores.
__global__ void k_h(const float* __restrict__ ea, const float* __restrict__ w1,
                    const float* __restrict__ b1) {
    __shared__ float ssum[2 * HID];
    __shared__ float sst[256 * (HID + 1)];
    const int tid  = threadIdx.x;
    const int lane = tid & 31;
    const int p    = blockIdx.x * 256 + tid;
    if (tid < 2 * HID) ssum[tid] = 0.f;

    float h[HID];
    if (p < EE) {
        int e = d_perm[p];
        float a0 = ea[3 * e + 0], a1 = ea[3 * e + 1], a2 = ea[3 * e + 2];
#pragma unroll
        for (int k = 0; k < HID; k++)
            h[k] = fmaf(a0, __ldg(&w1[k]),
                   fmaf(a1, __ldg(&w1[HID + k]),
                   fmaf(a2, __ldg(&w1[2 * HID + k]), __ldg(&b1[k]))));
    } else {
#pragma unroll
        for (int k = 0; k < HID; k++) h[k] = 0.f;
    }
    __syncthreads();   // ssum zeroed

    // warp reduction per column, lane0 -> smem atomics
#pragma unroll
    for (int k = 0; k < HID; k++) {
        float s = h[k], q = h[k] * h[k];
#pragma unroll
        for (int off = 16; off; off >>= 1) {
            s += __shfl_down_sync(0xffffffffu, s, off);
            q += __shfl_down_sync(0xffffffffu, q, off);
        }
        if (lane == 0) {
            atomicAdd(&ssum[k],       s);
            atomicAdd(&ssum[HID + k], q);
        }
        sst[tid * (HID + 1) + k] = h[k];
    }
    __syncthreads();

    // coalesced stores of the block's 256*25 h values
    size_t blockBase = (size_t)blockIdx.x * 256 * HID;
    for (int i = tid; i < 256 * HID; i += 256) {
        size_t gp = blockBase + i;
        if (gp < (size_t)EE * HID)
            d_h[gp] = sst[(i / HID) * (HID + 1) + (i % HID)];
    }
    if (tid < 2 * HID) atomicAdd(&d_sum[tid], (double)ssum[tid]);
}

// BN fold -> scale/shift, then re-zero stats for next layer
__global__ void k_bn(const float* __restrict__ g, const float* __restrict__ be) {
    int k = threadIdx.x;
    if (k < HID) {
        double mu  = d_sum[k] / (double)EE;
        double var = d_sum[HID + k] / (double)EE - mu * mu;
        float rs = rsqrtf((float)var + BEPS);
        float sc = rs * g[k];
        d_scale[k] = sc;
        d_shift[k] = be[k] - (float)mu * sc;
        d_sum[k] = 0.0;
        d_sum[HID + k] = 0.0;
    }
}

// ---------------- per-node precompute y[n,k,o] + xb, zero agg ----------------
template <int DIN>
__global__ void k_y(const float* __restrict__ xin_ext, int use_ext,
                    const float* __restrict__ w2, const float* __restrict__ b2) {
    extern __shared__ float sm[];
    float* w2s = sm;
    float* b2s = w2s + HID * DIN * DOUT;
    float* xs  = b2s + DIN * DOUT;
    const float* xin = use_ext ? xin_ext : d_x0;
    int tid = threadIdx.x;
    for (int i = tid; i < HID * DIN * DOUT; i += blockDim.x) w2s[i] = w2[i];
    for (int i = tid; i < DIN * DOUT; i += blockDim.x)       b2s[i] = b2[i];
    __syncthreads();

    for (int n0 = blockIdx.x * NT; n0 < NN; n0 += gridDim.x * NT) {
        for (int i = tid; i < NT * DIN; i += blockDim.x) {
            int n = n0 + i / DIN;
            xs[i] = (n < NN) ? xin[(size_t)n * DIN + (i % DIN)] : 0.f;
        }
        __syncthreads();

        for (int p = tid; p < HID * DOUT; p += blockDim.x) {
            int k = p / DOUT, o = p % DOUT;
            float a0 = 0.f, a1 = 0.f, a2 = 0.f, a3 = 0.f;
#pragma unroll
            for (int i = 0; i < DIN; i++) {
                float w = w2s[(k * DIN + i) * DOUT + o];
                a0 = fmaf(xs[0 * DIN + i], w, a0);
                a1 = fmaf(xs[1 * DIN + i], w, a1);
                a2 = fmaf(xs[2 * DIN + i], w, a2);
                a3 = fmaf(xs[3 * DIN + i], w, a3);
            }
            if (n0 + 0 < NN) d_y[((size_t)(n0 + 0) * HID + k) * DOUT + o] = a0;
            if (n0 + 1 < NN) d_y[((size_t)(n0 + 1) * HID + k) * DOUT + o] = a1;
            if (n0 + 2 < NN) d_y[((size_t)(n0 + 2) * HID + k) * DOUT + o] = a2;
            if (n0 + 3 < NN) d_y[((size_t)(n0 + 3) * HID + k) * DOUT + o] = a3;
        }
        for (int p = tid; p < NT * DOUT; p += blockDim.x) {
            int t = p / DOUT, o = p % DOUT;
            int n = n0 + t;
            if (n < NN) {
                float acc = 0.f;
#pragma unroll
                for (int i = 0; i < DIN; i++)
                    acc = fmaf(xs[t * DIN + i], b2s[i * DOUT + o], acc);
                d_xb[n * DOUT + o]  = acc;
                d_agg[n * DOUT + o] = 0.f;
            }
        }
        __syncthreads();
    }
}

// ---------------- messages: warp per SOURCE node, y row loaded once ----------
__global__ void k_msg() {
    int gw   = (blockIdx.x * blockDim.x + threadIdx.x) >> 5;
    int lane = threadIdx.x & 31;
    if (gw >= NN) return;
    int s   = gw;
    int beg = d_start[s], end = d_start[s + 1];
    if (beg == end) return;

    float sc = 1.f, sh = 0.f;
    if (lane < HID) { sc = d_scale[lane]; sh = d_shift[lane]; }
    float xb = d_xb[s * DOUT + lane];
    float yreg[HID];
#pragma unroll
    for (int k = 0; k < HID; k++)
        yreg[k] = d_y[((size_t)s * HID + k) * DOUT + lane];

    for (int p = beg; p < end; p++) {
        float hv = 0.f;
        if (lane < HID) hv = d_h[(size_t)p * HID + lane];
        hv = fmaxf(fmaf(hv, sc, sh), 0.f);                 // BN + relu
        float m = xb;
#pragma unroll
        for (int k = 0; k < HID; k++)
            m = fmaf(__shfl_sync(0xffffffffu, hv, k), yreg[k], m);
        atomicAdd(&d_agg[d_dsts[p] * DOUT + lane], m);
    }
}

// ---------------- node update ------------------------------------------------
template <int DIN>
__global__ void k_x(const float* __restrict__ xin_ext, int use_ext,
                    const float* __restrict__ wr, const float* __restrict__ bc,
                    int outsel) {
    int idx = blockIdx.x * blockDim.x + threadIdx.x;
    if (idx >= NN * DOUT) return;
    int n = idx / DOUT, o = idx % DOUT;
    const float* xin = use_ext ? xin_ext : d_x0;
    float root = __ldg(&bc[o]);
#pragma unroll
    for (int i = 0; i < DIN; i++)
        root = fmaf(xin[(size_t)n * DIN + i], __ldg(&wr[i * DOUT + o]), root);
    float dg = fmaxf(d_deg[n], 1.f);
    float v = d_agg[idx] / dg + root;
    v = (v > 0.f) ? v : expm1f(v);
    (outsel ? d_x1 : d_x0)[idx] = v;
}

// ---------------- pool + fc --------------------------------------------------
__global__ void kp_acc(const int* __restrict__ batch) {
    int gw   = (blockIdx.x * blockDim.x + threadIdx.x) >> 5;
    int lane = threadIdx.x & 31;
    if (gw >= NN) return;
    int b = batch[gw];
    atomicAdd(&d_gsum[b * DOUT + lane], d_x1[gw * DOUT + lane]);
    if (lane == 0) atomicAdd(&d_gcnt[b], 1.f);
}

__global__ void kp_out(const float* __restrict__ wfc, const float* __restrict__ bfc,
                       float* __restrict__ out) {
    int g = threadIdx.x;
    if (g < GG) {
        float c = fmaxf(d_gcnt[g], 1.f);
        float acc = 0.f;
#pragma unroll
        for (int o = 0; o < DOUT; o++)
            acc = fmaf(d_gsum[g * DOUT + o] / c, __ldg(&wfc[o]), acc);
        out[g] = acc + bfc[0];
    }
}

// ---------------- launch -----------------------------------------------------
extern "C" void kernel_launch(void* const* d_in, const int* in_sizes, int n_in,
                              void* d_out, int out_size) {
    (void)in_sizes; (void)n_in; (void)out_size;
    const float* x     = (const float*)d_in[0];
    const float* ea    = (const float*)d_in[1];
    const int*   ei    = (const int*)d_in[2];
    const int*   batch = (const int*)d_in[3];
    const float* w1_0 = (const float*)d_in[4];
    const float* b1_0 = (const float*)d_in[5];
    const float* g_0  = (const float*)d_in[6];
    const float* be_0 = (const float*)d_in[7];
    const float* w2_0 = (const float*)d_in[8];
    const float* b2_0 = (const float*)d_in[9];
    const float* wr_0 = (const float*)d_in[10];
    const float* bc_0 = (const float*)d_in[11];
    const float* w1_1 = (const float*)d_in[12];
    const float* b1_1 = (const float*)d_in[13];
    const float* g_1  = (const float*)d_in[14];
    const float* be_1 = (const float*)d_in[15];
    const float* w2_1 = (const float*)d_in[16];
    const float* b2_1 = (const float*)d_in[17];
    const float* wr_1 = (const float*)d_in[18];
    const float* bc_1 = (const float*)d_in[19];
    const float* wfc  = (const float*)d_in[20];
    const float* bfc  = (const float*)d_in[21];
    float* out = (float*)d_out;

    cudaFuncSetAttribute(k_y<16>, cudaFuncAttributeMaxDynamicSharedMemorySize, 64 * 1024);
    cudaFuncSetAttribute(k_y<32>, cudaFuncAttributeMaxDynamicSharedMemorySize, 112 * 1024);
    int smem0 = (HID * 16 * DOUT + 16 * DOUT + NT * 16) * (int)sizeof(float);
    int smem1 = (HID * 32 * DOUT + 32 * DOUT + NT * 32) * (int)sizeof(float);

    // ---- graph prologue: degrees + CSR-by-src ----
    k_init<<<(GG * DOUT + 255) / 256 > (NN + 255) / 256 ? (GG * DOUT + 255) / 256
                                                        : (NN + 255) / 256, 256>>>();
    k_deg<<<(EE + 255) / 256, 256>>>(ei);
    k_scan<<<1, 1024>>>();
    k_scatter<<<(EE + 255) / 256, 256>>>(ei);

    // ---- layer 0 (din=16) ----
    k_h<<<(EE + 255) / 256, 256>>>(ea, w1_0, b1_0);
    k_bn<<<1, 32>>>(g_0, be_0);
    k_y<16><<<296, 256, smem0>>>(x, 1, w2_0, b2_0);
    k_msg<<<(NN * 32 + 255) / 256, 256>>>();
    k_x<16><<<(NN * DOUT + 255) / 256, 256>>>(x, 1, wr_0, bc_0, 0);

    // ---- layer 1 (din=32) ----
    k_h<<<(EE + 255) / 256, 256>>>(ea, w1_1, b1_1);
    k_bn<<<1, 32>>>(g_1, be_1);
    k_y<32><<<296, 256, smem1>>>(nullptr, 0, w2_1, b2_1);
    k_msg<<<(NN * 32 + 255) / 256, 256>>>();
    k_x<32><<<(NN * DOUT + 255) / 256, 256>>>(nullptr, 0, wr_1, bc_1, 1);

    // ---- pool + fc ----
    kp_acc<<<(NN * 32 + 255) / 256, 256>>>(batch);
    kp_out<<<1, 128>>>(wfc, bfc, out);
}